// round 14
// baseline (speedup 1.0000x reference)
#include <cuda_runtime.h>
#include <cuda_fp16.h>
#include <math.h>
#include <stdint.h>

#define B_   8
#define T_   4096
#define D_   256
#define M_   1024
#define CTX_ 7
#define L_   4102
#define LP   4104
#define BT_  32768
#define KC_  1792

#define OFF_CP  8388608
#define OFF_PP  8388609
#define OFF_IND 8388610

__device__ __half g_ZH[B_ * D_ * LP], g_ZL[B_ * D_ * LP];
__device__ __half g_COH[B_ * D_ * T_], g_COL[B_ * D_ * T_];
__device__ float  g_cur[BT_ * D_];
__device__ uint32_t g_WCH[256 * 896], g_WCL[256 * 896];   // PLAIN (conv A)
__device__ uint32_t g_XH[BT_ * 128],  g_XL[BT_ * 128];    // PLAIN (fuse1 A staging)
__device__ uint32_t g_CH[BT_ * 128],  g_CL[BT_ * 128];    // PLAIN (dist A)
__device__ uint32_t g_EH[M_ * 128],   g_EL[M_ * 128];     // colmap (dist B LDG)
__device__ uint32_t g_EPH[M_ * 128],  g_EPL[M_ * 128];    // PLAIN (fuse2 A staging)
__device__ uint32_t g_W1H[256 * 256], g_W1L[256 * 256];   // colmap (fuse B LDG)
__device__ uint32_t g_W2H[256 * 256], g_W2L[256 * 256];
__device__ float g_en[M_];
__device__ float g_part[B_][64];
__device__ int   g_idx[BT_];
__device__ int   g_hist[M_];
__device__ float g_avg[M_];

__device__ __forceinline__ float prelu_f(float v, float a) { return v >= 0.f ? v : a * v; }

__device__ __forceinline__ float neg_log_acc(float u) {
    if (u > 0.9f) {
        float d = 1.0f - u;
        return d * (1.f + d * (0.5f + d * (0.33333334f + d * (0.25f + d * (0.2f + d * 0.16666667f)))));
    }
    return -logf(u);
}

__device__ __forceinline__ uint32_t pack_h2(__half a, __half b) {
    __half2 h = __halves2half2(a, b);
    return *(uint32_t*)&h;
}
__device__ __forceinline__ uint32_t smem_u32(const void* p) {
    uint32_t a;
    asm("{ .reg .u64 t; cvta.to.shared.u64 t, %1; cvt.u32.u64 %0, t; }" : "=r"(a) : "l"(p));
    return a;
}
__device__ __forceinline__ void mma16816(float* d, const uint32_t* a, const uint32_t* b) {
    asm volatile(
        "mma.sync.aligned.m16n8k16.row.col.f32.f16.f16.f32 "
        "{%0,%1,%2,%3}, {%4,%5,%6,%7}, {%8,%9}, {%0,%1,%2,%3};"
        : "+f"(d[0]), "+f"(d[1]), "+f"(d[2]), "+f"(d[3])
        : "r"(a[0]), "r"(a[1]), "r"(a[2]), "r"(a[3]), "r"(b[0]), "r"(b[1]));
}
__device__ __forceinline__ void ldsm4(uint32_t* r, uint32_t addr) {
    asm volatile("ldmatrix.sync.aligned.m8n8.x4.shared.b16 {%0,%1,%2,%3}, [%4];"
                 : "=r"(r[0]), "=r"(r[1]), "=r"(r[2]), "=r"(r[3]) : "r"(addr));
}
__device__ __forceinline__ void split_store(uint32_t* H, uint32_t* L, float x0, float x1) {
    __half h0 = __float2half_rn(x0), h1 = __float2half_rn(x1);
    __half l0 = __float2half_rn(x0 - __half2float(h0));
    __half l1 = __float2half_rn(x1 - __half2float(h1));
    *H = pack_h2(h0, h1);
    *L = pack_h2(l0, l1);
}
__device__ __forceinline__ int colmap(int p) {
    int s = p >> 3, r = p & 7;
    return 8 * s + ((r & 4) ? ((r - 4) * 2 + 1) : (r * 2));
}

// ---------------- merged prep: stats zero, all splits, |E|^2, scale partials ----------------
__global__ void k_prep(const float* __restrict__ emb, const float* __restrict__ wf1,
                       const float* __restrict__ wf2, const float* __restrict__ x,
                       const float* __restrict__ wctx) {
    int tid = blockIdx.x * blockDim.x + threadIdx.x;
    int stride = gridDim.x * blockDim.x;
    if (tid < M_) { g_hist[tid] = 0; g_avg[tid] = 0.f; }
    for (int idx = tid; idx < M_ * 128; idx += stride) {
        int m = idx >> 7, p = idx & 127;
        float2 v = *(const float2*)&emb[(size_t)m * D_ + 2 * p];
        int c = m * 128 + colmap(p);
        split_store(&g_EH[c], &g_EL[c], v.x, v.y);
        split_store(&g_EPH[idx], &g_EPL[idx], v.x, v.y);
    }
    for (int idx = tid; idx < 256 * 256; idx += stride) {
        int o = idx >> 8, p = idx & 255;
        int c = o * 256 + colmap(p);
        float2 v1 = *(const float2*)&wf1[(size_t)o * 512 + 2 * p];
        split_store(&g_W1H[c], &g_W1L[c], v1.x, v1.y);
        float2 v2 = *(const float2*)&wf2[(size_t)o * 512 + 2 * p];
        split_store(&g_W2H[c], &g_W2L[c], v2.x, v2.y);
    }
    for (int idx = tid; idx < 256 * 896; idx += stride) {
        int o = idx / 896, p = idx - o * 896;
        float2 v = *(const float2*)&wctx[(size_t)o * KC_ + 2 * p];
        split_store(&g_WCH[idx], &g_WCL[idx], v.x, v.y);
    }
    for (int idx = tid; idx < BT_ * 128; idx += stride) {
        int tok = idx >> 7, p = idx & 127;
        float2 v = *(const float2*)&x[(size_t)tok * D_ + 2 * p];
        split_store(&g_XH[idx], &g_XL[idx], v.x, v.y);
    }
    int w = tid >> 5, lane = tid & 31;
    if (w < M_) {
        const float* er = emb + (size_t)w * D_;
        double s = 0.0;
        for (int d = lane; d < D_; d += 32) { double v = (double)er[d]; s += v * v; }
        for (int off = 16; off; off >>= 1) s += __shfl_xor_sync(0xffffffffu, s, off);
        if (lane == 0) g_en[w] = (float)s;
    }
    // scale partials (bit-identical to old k_scale with grid 64 x B)
    {
        int b = blockIdx.x >> 6, sub = blockIdx.x & 63;
        const float* xb = x + (size_t)b * T_ * D_;
        const int n = (T_ - 1) * D_;
        float s = 0.f;
        for (int i = sub * 256 + threadIdx.x; i < n; i += 64 * 256) {
            float v = xb[i]; s += v * v;
        }
        __shared__ float red[256];
        red[threadIdx.x] = s; __syncthreads();
        for (int st = 128; st > 0; st >>= 1) {
            if (threadIdx.x < st) red[threadIdx.x] += red[threadIdx.x + st];
            __syncthreads();
        }
        if (threadIdx.x == 0) g_part[b][sub] = red[0];
    }
}

// ---------------- noisy context (coef computed inline, bit-identical) ----------------
__global__ void k_ctxn(const float* __restrict__ x, const float* __restrict__ noise,
                       const int* __restrict__ epo_i) {
    __shared__ float xs[32][33];
    __shared__ float s_coef;
    int b = blockIdx.z, bd = blockIdx.y * 32, bj = blockIdx.x * 32;
    if (threadIdx.y == 0) {
        int lane = threadIdx.x;
        float s = g_part[b][lane] + g_part[b][lane + 32];
        for (int off = 16; off; off >>= 1) s += __shfl_xor_sync(0xffffffffu, s, off);
        if (lane == 0) {
            int ei = *epo_i;
            double ef = (ei >= 0 && ei <= 1000000) ? (double)ei : (double)__int_as_float(ei);
            double mean = (double)s / (double)(D_ * L_);
            s_coef = (float)(0.5 * exp2(-ef / 10.0) * sqrt(mean));
        }
    }
    int t = bj + threadIdx.y - CTX_;
    float v = 0.f;
    if (t >= 0 && t < T_ - 1)
        v = x[((size_t)b * T_ + t) * D_ + bd + threadIdx.x];
    xs[threadIdx.y][threadIdx.x] = v;
    __syncthreads();
    int j = bj + threadIdx.x;
    if (j < L_) {
        int d = bd + threadIdx.y;
        float z = xs[threadIdx.x][threadIdx.y] + s_coef * noise[((size_t)b * D_ + d) * L_ + j];
        __half h = __float2half_rn(z);
        __half l = __float2half_rn(z - __half2float(h));
        size_t off = ((size_t)b * D_ + d) * LP + j;
        g_ZH[off] = h; g_ZL[off] = l;
    }
}

// ---------------- conv: M=256 CTA tile, 64x64 warp tiles, LDSM fragments ----------------
__global__ __launch_bounds__(256, 1) void k_convM() {
    __shared__ uint32_t AH[256][20], AL[256][20], BH[128][20], BL[128][20];
    int tid = threadIdx.x, wid = tid >> 5, lane = tid & 31;
    int bn = blockIdx.x * 128, b = blockIdx.z;
    const __half* zh = g_ZH + (size_t)b * D_ * LP;
    const __half* zl = g_ZL + (size_t)b * D_ * LP;
    int wm = wid >> 1, wn = wid & 1;      // 4 x 2 warps
    int gr = lane >> 2, ctid = lane & 3;

    float acc[4][8][4];
#pragma unroll
    for (int i = 0; i < 4; i++)
#pragma unroll
        for (int j = 0; j < 8; j++)
#pragma unroll
            for (int r = 0; r < 4; r++) acc[i][j][r] = 0.f;

    uint32_t sAH = smem_u32(AH), sAL = smem_u32(AL);
    uint32_t sBH = smem_u32(BH), sBL = smem_u32(BL);
    uint32_t aAddr[4];
#pragma unroll
    for (int mf = 0; mf < 4; mf++) {
        int row = wm * 64 + mf * 16 + ((lane >> 3) & 1) * 8 + (lane & 7);
        aAddr[mf] = (uint32_t)row * 80 + ((lane >> 4) & 1) * 16;
    }
    uint32_t bAddr[4];
#pragma unroll
    for (int nfp = 0; nfp < 4; nfp++) {
        int row = wn * 64 + nfp * 16 + ((lane >> 4) & 1) * 8 + (lane & 7);
        bAddr[nfp] = (uint32_t)row * 80 + ((lane >> 3) & 1) * 16;
    }
    int bt = tid & 127, ph = tid >> 7;

    for (int c = 0; c < 56; c++) {
        __syncthreads();
        // A: 256 rows x 16 pairs, coalesced-ish uint4 copies
#pragma unroll
        for (int q = 0; q < 4; q++) {
            int i = tid + q * 256;
            int row = i >> 2, cq = (i & 3) * 4;
            *(uint4*)&AH[row][cq] = *(const uint4*)&g_WCH[(size_t)row * 896 + c * 16 + cq];
            *(uint4*)&AL[row][cq] = *(const uint4*)&g_WCL[(size_t)row * 896 + c * 16 + cq];
        }
        // B: pack half pairs, plain order (R12-proven)
#pragma unroll
        for (int p = 0; p < 8; p++) {
            int pl = 8 * ph + p;
            int k0 = 32 * c + 2 * pl;
            int ci0 = k0 / 7, ck0 = k0 - 7 * ci0;
            int ci1 = ci0, ck1 = ck0 + 1;
            if (ck1 == 7) { ck1 = 0; ci1++; }
            int j0 = ci0 * LP + bn + bt + ck0;
            int j1 = ci1 * LP + bn + bt + ck1;
            BH[bt][pl] = pack_h2(zh[j0], zh[j1]);
            BL[bt][pl] = pack_h2(zl[j0], zl[j1]);
        }
        __syncthreads();
#pragma unroll
        for (int ks = 0; ks < 2; ks++) {
            uint32_t aH[4][4], aL[4][4];
#pragma unroll
            for (int mf = 0; mf < 4; mf++) {
                ldsm4(aH[mf], sAH + aAddr[mf] + ks * 32);
                ldsm4(aL[mf], sAL + aAddr[mf] + ks * 32);
            }
#pragma unroll
            for (int nfp = 0; nfp < 4; nfp++) {
                uint32_t bh4[4], bl4[4];
                ldsm4(bh4, sBH + bAddr[nfp] + ks * 32);
                ldsm4(bl4, sBL + bAddr[nfp] + ks * 32);
#pragma unroll
                for (int half = 0; half < 2; half++) {
                    int nf = nfp * 2 + half;
                    uint32_t bh[2] = {bh4[half * 2], bh4[half * 2 + 1]};
                    uint32_t bl[2] = {bl4[half * 2], bl4[half * 2 + 1]};
#pragma unroll
                    for (int mf = 0; mf < 4; mf++) {
                        mma16816(acc[mf][nf], aH[mf], bl);
                        mma16816(acc[mf][nf], aL[mf], bh);
                        mma16816(acc[mf][nf], aH[mf], bh);
                    }
                }
            }
        }
    }
#pragma unroll
    for (int mf = 0; mf < 4; mf++) {
        int o0 = wm * 64 + mf * 16 + gr;
#pragma unroll
        for (int nf = 0; nf < 8; nf++) {
            int t0 = bn + wn * 64 + nf * 8 + 2 * ctid;
            size_t b0 = ((size_t)b * D_ + o0) * T_ + t0;
            size_t b8 = ((size_t)b * D_ + o0 + 8) * T_ + t0;
            split_store((uint32_t*)&g_COH[b0], (uint32_t*)&g_COL[b0],
                        acc[mf][nf][0], acc[mf][nf][1]);
            split_store((uint32_t*)&g_COH[b8], (uint32_t*)&g_COL[b8],
                        acc[mf][nf][2], acc[mf][nf][3]);
        }
    }
}

// ---------------- fuse (R13): plain staging + LDSM A; B direct LDG colmap ----------------
template<int WHICH>
__global__ __launch_bounds__(256) void k_fuse2(const float* __restrict__ pa,
                                               float* __restrict__ outp) {
    __shared__ uint32_t AH[128][20], AL[128][20];
    __shared__ int idxS[128];
    int tid = threadIdx.x, wid = tid >> 5, lane = tid & 31;
    int tok0 = blockIdx.x * 128;
    int b = tok0 >> 12, t0g = tok0 & (T_ - 1);
    int wm = wid >> 2, wn = wid & 3;
    int gr = lane >> 2, ctid = lane & 3;
    if (WHICH == 1 && tid < 128) idxS[tid] = g_idx[tok0 + tid];

    float acc[4][8][4];
#pragma unroll
    for (int i = 0; i < 4; i++)
#pragma unroll
        for (int j = 0; j < 8; j++)
#pragma unroll
            for (int r = 0; r < 4; r++) acc[i][j][r] = 0.f;

    const uint32_t* WH = (WHICH == 0) ? g_W1H : g_W2H;
    const uint32_t* WL = (WHICH == 0) ? g_W1L : g_W2L;
    float* optr = (WHICH == 0) ? g_cur : outp;
    uint32_t sAH = smem_u32(AH), sAL = smem_u32(AL);
    uint32_t aAddr[4];
#pragma unroll
    for (int mf = 0; mf < 4; mf++) {
        int row = wm * 64 + mf * 16 + ((lane >> 3) & 1) * 8 + (lane & 7);
        aAddr[mf] = (uint32_t)row * 80 + ((lane >> 4) & 1) * 16;
    }
    int stok = tid >> 1, sh8 = (tid & 1) * 8;
    int bt = tid & 127, ph = tid >> 7;
    __syncthreads();

    for (int cc = 0; cc < 16; cc++) {
        __syncthreads();
        if (cc < 8) {
            size_t rb = (WHICH == 0) ? (size_t)(tok0 + stok) * 128 : (size_t)idxS[stok] * 128;
            const uint32_t* sH = (WHICH == 0) ? &g_XH[rb + 16 * cc + sh8] : &g_EPH[rb + 16 * cc + sh8];
            const uint32_t* sL = (WHICH == 0) ? &g_XL[rb + 16 * cc + sh8] : &g_EPL[rb + 16 * cc + sh8];
            *(uint4*)&AH[stok][sh8]     = *(const uint4*)sH;
            *(uint4*)&AH[stok][sh8 + 4] = *(const uint4*)(sH + 4);
            *(uint4*)&AL[stok][sh8]     = *(const uint4*)sL;
            *(uint4*)&AL[stok][sh8 + 4] = *(const uint4*)(sL + 4);
        } else {
#pragma unroll
            for (int p = 0; p < 8; p++) {
                int pl = 8 * ph + p;
                int ch = cc * 32 - 256 + 2 * pl;
                size_t i0 = ((size_t)b * D_ + ch) * T_ + t0g + bt;
                size_t i1 = i0 + T_;
                AH[bt][pl] = pack_h2(g_COH[i0], g_COH[i1]);
                AL[bt][pl] = pack_h2(g_COL[i0], g_COL[i1]);
            }
        }
        __syncthreads();
#pragma unroll
        for (int ks = 0; ks < 2; ks++) {
            int sg = cc * 2 + ks;
            uint32_t aH[4][4], aL[4][4];
#pragma unroll
            for (int mf = 0; mf < 4; mf++) {
                ldsm4(aH[mf], sAH + aAddr[mf] + ks * 32);
                ldsm4(aL[mf], sAL + aAddr[mf] + ks * 32);
            }
#pragma unroll
            for (int nf = 0; nf < 8; nf++) {
                int n = wn * 64 + nf * 8 + gr;
                uint2 bh2 = *(const uint2*)&WH[(size_t)n * 256 + 8 * sg + 2 * ctid];
                uint2 bl2 = *(const uint2*)&WL[(size_t)n * 256 + 8 * sg + 2 * ctid];
                uint32_t bh[2] = {bh2.x, bh2.y}, bl[2] = {bl2.x, bl2.y};
#pragma unroll
                for (int mf = 0; mf < 4; mf++) {
                    mma16816(acc[mf][nf], aH[mf], bl);
                    mma16816(acc[mf][nf], aL[mf], bh);
                    mma16816(acc[mf][nf], aH[mf], bh);
                }
            }
        }
    }
    float av = *pa;
#pragma unroll
    for (int mf = 0; mf < 4; mf++) {
        int row = tok0 + wm * 64 + mf * 16 + gr;
#pragma unroll
        for (int nf = 0; nf < 8; nf++) {
            int col = wn * 64 + nf * 8 + 2 * ctid;
            float v0 = prelu_f(acc[mf][nf][0], av), v1 = prelu_f(acc[mf][nf][1], av);
            float v2 = prelu_f(acc[mf][nf][2], av), v3 = prelu_f(acc[mf][nf][3], av);
            *(float2*)&optr[(size_t)row * D_ + col]       = make_float2(v0, v1);
            *(float2*)&optr[(size_t)(row + 8) * D_ + col] = make_float2(v2, v3);
            if (WHICH == 0) {
                int cm = wn * 32 + nf * 4 + ctid;
                split_store(&g_CH[(size_t)row * 128 + cm], &g_CL[(size_t)row * 128 + cm], v0, v1);
                split_store(&g_CH[(size_t)(row + 8) * 128 + cm], &g_CL[(size_t)(row + 8) * 128 + cm], v2, v3);
            }
        }
    }
}

// ---------------- dist (R12-proven) ----------------
__global__ __launch_bounds__(256) void k_distM(const float* __restrict__ gu,
                                               float* __restrict__ dout) {
    __shared__ uint32_t AH[32][132], AL[32][132];
    __shared__ float pv[32][8];
    __shared__ int   pi[32][8];
    __shared__ float rs[32], zs[32], cns[32];
    int tid = threadIdx.x, wid = tid >> 5, lane = tid & 31;
    int wn = wid;
    int gr = lane >> 2, ctid = lane & 3;
    int row0g = blockIdx.x * 32;

    for (int idx = tid; idx < 32 * 32; idx += 256) {
        int row = idx >> 5, q = (idx & 31) * 4;
        *(uint4*)&AH[row][q] = *(const uint4*)&g_CH[(size_t)(row0g + row) * 128 + q];
        *(uint4*)&AL[row][q] = *(const uint4*)&g_CL[(size_t)(row0g + row) * 128 + q];
    }
#pragma unroll
    for (int i = 0; i < 4; i++) {
        const float* cr = g_cur + (size_t)(row0g + wid * 4 + i) * D_;
        float s = 0.f;
#pragma unroll
        for (int q = 0; q < 8; q++) { float v = cr[lane + q * 32]; s += v * v; }
#pragma unroll
        for (int off = 16; off; off >>= 1) s += __shfl_xor_sync(0xffffffffu, s, off);
        if (lane == 0) cns[wid * 4 + i] = s;
    }
    __syncthreads();

    uint32_t sAH = smem_u32(AH), sAL = smem_u32(AL);
    uint32_t aAddr[2];
#pragma unroll
    for (int mf = 0; mf < 2; mf++) {
        int row = mf * 16 + ((lane >> 3) & 1) * 8 + (lane & 7);
        aAddr[mf] = (uint32_t)row * 528 + ((lane >> 4) & 1) * 16;
    }

    float acc[2][16][4];
#pragma unroll
    for (int i = 0; i < 2; i++)
#pragma unroll
        for (int j = 0; j < 16; j++)
#pragma unroll
            for (int r = 0; r < 4; r++) acc[i][j][r] = 0.f;

#pragma unroll
    for (int s = 0; s < 16; s++) {
        uint32_t aH[2][4], aL[2][4];
#pragma unroll
        for (int mf = 0; mf < 2; mf++) {
            ldsm4(aH[mf], sAH + aAddr[mf] + s * 32);
            ldsm4(aL[mf], sAL + aAddr[mf] + s * 32);
        }
#pragma unroll
        for (int nf = 0; nf < 16; nf++) {
            int n = wn * 128 + nf * 8 + gr;
            uint2 bh2 = *(const uint2*)&g_EH[(size_t)n * 128 + 8 * s + 2 * ctid];
            uint2 bl2 = *(const uint2*)&g_EL[(size_t)n * 128 + 8 * s + 2 * ctid];
            uint32_t bh[2] = {bh2.x, bh2.y}, bl[2] = {bl2.x, bl2.y};
#pragma unroll
            for (int mf = 0; mf < 2; mf++) {
                mma16816(acc[mf][nf], aH[mf], bl);
                mma16816(acc[mf][nf], aL[mf], bh);
                mma16816(acc[mf][nf], aH[mf], bh);
            }
        }
    }

#pragma unroll
    for (int mf = 0; mf < 2; mf++)
#pragma unroll
        for (int nf = 0; nf < 16; nf++) {
            float2 e2 = *(const float2*)&g_en[wn * 128 + nf * 8 + 2 * ctid];
            float clo = cns[mf * 16 + gr], chi = cns[mf * 16 + gr + 8];
            acc[mf][nf][0] = -((clo + e2.x) - 2.f * acc[mf][nf][0]);
            acc[mf][nf][1] = -((clo + e2.y) - 2.f * acc[mf][nf][1]);
            acc[mf][nf][2] = -((chi + e2.x) - 2.f * acc[mf][nf][2]);
            acc[mf][nf][3] = -((chi + e2.y) - 2.f * acc[mf][nf][3]);
        }

    int rid[4] = {gr, gr + 8, 16 + gr, 24 + gr};

#pragma unroll
    for (int rr = 0; rr < 4; rr++) {
        int mf = rr >> 1, h = rr & 1;
        float mv = -3.4e38f; int mi = 0;
#pragma unroll
        for (int nf = 0; nf < 16; nf++) {
            int cb = wn * 128 + nf * 8 + 2 * ctid;
            float v0 = acc[mf][nf][h * 2], v1 = acc[mf][nf][h * 2 + 1];
            if (v0 > mv) { mv = v0; mi = cb; }
            if (v1 > mv) { mv = v1; mi = cb + 1; }
        }
#pragma unroll
        for (int off = 1; off <= 2; off <<= 1) {
            float ov = __shfl_xor_sync(0xffffffffu, mv, off);
            int   oi = __shfl_xor_sync(0xffffffffu, mi, off);
            if (ov > mv || (ov == mv && oi < mi)) { mv = ov; mi = oi; }
        }
        if (ctid == 0) { pv[rid[rr]][wn] = mv; pi[rid[rr]][wn] = mi; }
    }
    __syncthreads();
    if (tid < 32) {
        float mv = pv[tid][0]; int mi = pi[tid][0];
#pragma unroll
        for (int w = 1; w < 8; w++) {
            float ov = pv[tid][w]; int oi = pi[tid][w];
            if (ov > mv || (ov == mv && oi < mi)) { mv = ov; mi = oi; }
        }
        atomicAdd(&g_hist[mi], 1);
        rs[tid] = mv;
    }
    __syncthreads();

#pragma unroll
    for (int rr = 0; rr < 4; rr++) {
        int mf = rr >> 1, h = rr & 1;
        float rm = rs[rid[rr]];
        float s = 0.f;
#pragma unroll
        for (int nf = 0; nf < 16; nf++) {
            float e0 = __expf(acc[mf][nf][h * 2] - rm);
            float e1 = __expf(acc[mf][nf][h * 2 + 1] - rm);
            acc[mf][nf][h * 2] = e0; acc[mf][nf][h * 2 + 1] = e1;
            s += e0 + e1;
        }
#pragma unroll
        for (int off = 1; off <= 2; off <<= 1) s += __shfl_xor_sync(0xffffffffu, s, off);
        if (ctid == 0) pv[rid[rr]][wn] = s;
    }
    __syncthreads();
    if (tid < 32) {
        float z = 0.f;
#pragma unroll
        for (int w = 0; w < 8; w++) z += pv[tid][w];
        zs[tid] = 1.f / z;
    }
    __syncthreads();

    {
        float iz[4];
#pragma unroll
        for (int rr = 0; rr < 4; rr++) iz[rr] = zs[rid[rr]];
#pragma unroll
        for (int nf = 0; nf < 16; nf++) {
            float cs0 = acc[0][nf][0] * iz[0] + acc[0][nf][2] * iz[1]
                      + acc[1][nf][0] * iz[2] + acc[1][nf][2] * iz[3];
            float cs1 = acc[0][nf][1] * iz[0] + acc[0][nf][3] * iz[1]
                      + acc[1][nf][1] * iz[2] + acc[1][nf][3] * iz[3];
#pragma unroll
            for (int off = 4; off <= 16; off <<= 1) {
                cs0 += __shfl_xor_sync(0xffffffffu, cs0, off);
                cs1 += __shfl_xor_sync(0xffffffffu, cs1, off);
            }
            if (gr == 0) {
                int cb = wn * 128 + nf * 8 + 2 * ctid;
                atomicAdd(&g_avg[cb], cs0);
                atomicAdd(&g_avg[cb + 1], cs1);
            }
        }
    }

#pragma unroll
    for (int rr = 0; rr < 4; rr++) {
        int mf = rr >> 1, h = rr & 1;
        int row = row0g + rid[rr];
        float mv = -1.f; int mi = 0;
#pragma unroll
        for (int nf = 0; nf < 16; nf++) {
            int cb = wn * 128 + nf * 8 + 2 * ctid;
            float2 ug = *(const float2*)&gu[(size_t)row * M_ + cb];
            float u0 = fminf(fmaxf(ug.x, 1e-10f), 0.99999990f);
            float u1 = fminf(fmaxf(ug.y, 1e-10f), 0.99999990f);
            float t0 = neg_log_acc(u0), t1 = neg_log_acc(u1);
            float e0 = acc[mf][nf][h * 2], e1 = acc[mf][nf][h * 2 + 1];
            if (e0 > mv * t0) { mv = __fdividef(e0, t0); mi = cb; }
            if (e1 > mv * t1) { mv = __fdividef(e1, t1); mi = cb + 1; }
        }
#pragma unroll
        for (int off = 1; off <= 2; off <<= 1) {
            float ov = __shfl_xor_sync(0xffffffffu, mv, off);
            int   oi = __shfl_xor_sync(0xffffffffu, mi, off);
            if (ov > mv || (ov == mv && oi < mi)) { mv = ov; mi = oi; }
        }
        if (ctid == 0) { pv[rid[rr]][wn] = mv; pi[rid[rr]][wn] = mi; }
    }
    __syncthreads();
    if (tid < 32) {
        float mv = pv[tid][0]; int mi = pi[tid][0];
#pragma unroll
        for (int w = 1; w < 8; w++) {
            float ov = pv[tid][w]; int oi = pi[tid][w];
            if (ov > mv || (ov == mv && oi < mi)) { mv = ov; mi = oi; }
        }
        g_idx[row0g + tid] = mi;
        dout[OFF_IND + row0g + tid] = (float)mi;
    }
}

__global__ void k_perp(float* __restrict__ dout) {
    __shared__ float red[1024];
    int m = threadIdx.x;
    float p = (float)g_hist[m] / 32768.f;
    red[m] = -p * log2f(p + 1e-10f);
    __syncthreads();
    for (int st = 512; st > 0; st >>= 1) {
        if (m < st) red[m] += red[m + st];
        __syncthreads();
    }
    if (m == 0) dout[OFF_CP] = red[0];
    __syncthreads();
    float q = g_avg[m] / 32768.f;
    red[m] = -q * log2f(q + 1e-10f);
    __syncthreads();
    for (int st = 512; st > 0; st >>= 1) {
        if (m < st) red[m] += red[m + st];
        __syncthreads();
    }
    if (m == 0) dout[OFF_PP] = red[0];
}

extern "C" void kernel_launch(void* const* d_in, const int* in_sizes, int n_in,
                              void* d_out, int out_size) {
    const float* x     = (const float*)d_in[0];
    const float* noise = (const float*)d_in[1];
    const float* gu    = (const float*)d_in[2];
    const int*   epo   = (const int*)d_in[3];
    const float* emb   = (const float*)d_in[4];
    const float* wctx  = (const float*)d_in[5];
    const float* wf1   = (const float*)d_in[6];
    const float* a1    = (const float*)d_in[7];
    const float* wf2   = (const float*)d_in[8];
    const float* a2    = (const float*)d_in[9];
    float* out = (float*)d_out;

    k_prep<<<512, 256>>>(emb, wf1, wf2, x, wctx);                    // 0
    k_ctxn<<<dim3((L_ + 31) / 32, D_ / 32, B_), dim3(32, 32)>>>(x, noise, epo);  // 1
    k_convM<<<dim3(T_ / 128, 1, B_), 256>>>();                       // 2
    k_fuse2<0><<<BT_ / 128, 256>>>(a1, out);                         // 3 <- profiled slot
    k_distM<<<BT_ / 32, 256>>>(gu, out);                             // 4
    k_perp<<<1, 1024>>>(out);                                        // 5
    k_fuse2<1><<<BT_ / 128, 256>>>(a2, out);                         // 6
}

// round 15
// speedup vs baseline: 1.0300x; 1.0300x over previous
#include <cuda_runtime.h>
#include <cuda_fp16.h>
#include <math.h>
#include <stdint.h>

#define B_   8
#define T_   4096
#define D_   256
#define M_   1024
#define CTX_ 7
#define L_   4102
#define LP   4104
#define BT_  32768
#define KC_  1792

#define OFF_CP  8388608
#define OFF_PP  8388609
#define OFF_IND 8388610

__device__ __half g_ZH[B_ * D_ * LP], g_ZL[B_ * D_ * LP];
__device__ __half g_COH[B_ * D_ * T_], g_COL[B_ * D_ * T_];
__device__ float  g_cur[BT_ * D_];
__device__ uint32_t g_WCH[256 * 896], g_WCL[256 * 896];   // PLAIN (conv A)
__device__ uint32_t g_XH[BT_ * 128],  g_XL[BT_ * 128];    // PLAIN (fuse1 A staging)
__device__ uint32_t g_CH[BT_ * 128],  g_CL[BT_ * 128];    // PLAIN (dist A)
__device__ uint32_t g_EH[M_ * 128],   g_EL[M_ * 128];     // colmap (dist B LDG)
__device__ uint32_t g_EPH[M_ * 128],  g_EPL[M_ * 128];    // PLAIN (fuse2 A staging)
__device__ uint32_t g_W1H[256 * 256], g_W1L[256 * 256];   // colmap (fuse B LDG)
__device__ uint32_t g_W2H[256 * 256], g_W2L[256 * 256];
__device__ float g_en[M_];
__device__ float g_part[B_][64];
__device__ int   g_idx[BT_];
__device__ int   g_hist[M_];
__device__ float g_avg[M_];

__device__ __forceinline__ float prelu_f(float v, float a) { return v >= 0.f ? v : a * v; }

__device__ __forceinline__ float neg_log_acc(float u) {
    if (u > 0.9f) {
        float d = 1.0f - u;
        return d * (1.f + d * (0.5f + d * (0.33333334f + d * (0.25f + d * (0.2f + d * 0.16666667f)))));
    }
    return -logf(u);
}

__device__ __forceinline__ uint32_t pack_h2(__half a, __half b) {
    __half2 h = __halves2half2(a, b);
    return *(uint32_t*)&h;
}
__device__ __forceinline__ uint32_t smem_u32(const void* p) {
    uint32_t a;
    asm("{ .reg .u64 t; cvta.to.shared.u64 t, %1; cvt.u32.u64 %0, t; }" : "=r"(a) : "l"(p));
    return a;
}
__device__ __forceinline__ void mma16816(float* d, const uint32_t* a, const uint32_t* b) {
    asm volatile(
        "mma.sync.aligned.m16n8k16.row.col.f32.f16.f16.f32 "
        "{%0,%1,%2,%3}, {%4,%5,%6,%7}, {%8,%9}, {%0,%1,%2,%3};"
        : "+f"(d[0]), "+f"(d[1]), "+f"(d[2]), "+f"(d[3])
        : "r"(a[0]), "r"(a[1]), "r"(a[2]), "r"(a[3]), "r"(b[0]), "r"(b[1]));
}
__device__ __forceinline__ void ldsm4(uint32_t* r, uint32_t addr) {
    asm volatile("ldmatrix.sync.aligned.m8n8.x4.shared.b16 {%0,%1,%2,%3}, [%4];"
                 : "=r"(r[0]), "=r"(r[1]), "=r"(r[2]), "=r"(r[3]) : "r"(addr));
}
__device__ __forceinline__ void split_store(uint32_t* H, uint32_t* L, float x0, float x1) {
    __half h0 = __float2half_rn(x0), h1 = __float2half_rn(x1);
    __half l0 = __float2half_rn(x0 - __half2float(h0));
    __half l1 = __float2half_rn(x1 - __half2float(h1));
    *H = pack_h2(h0, h1);
    *L = pack_h2(l0, l1);
}
__device__ __forceinline__ int colmap(int p) {
    int s = p >> 3, r = p & 7;
    return 8 * s + ((r & 4) ? ((r - 4) * 2 + 1) : (r * 2));
}

// ---------------- merged prep ----------------
__global__ void k_prep(const float* __restrict__ emb, const float* __restrict__ wf1,
                       const float* __restrict__ wf2, const float* __restrict__ x,
                       const float* __restrict__ wctx) {
    int tid = blockIdx.x * blockDim.x + threadIdx.x;
    int stride = gridDim.x * blockDim.x;
    if (tid < M_) { g_hist[tid] = 0; g_avg[tid] = 0.f; }
    for (int idx = tid; idx < M_ * 128; idx += stride) {
        int m = idx >> 7, p = idx & 127;
        float2 v = *(const float2*)&emb[(size_t)m * D_ + 2 * p];
        int c = m * 128 + colmap(p);
        split_store(&g_EH[c], &g_EL[c], v.x, v.y);
        split_store(&g_EPH[idx], &g_EPL[idx], v.x, v.y);
    }
    for (int idx = tid; idx < 256 * 256; idx += stride) {
        int o = idx >> 8, p = idx & 255;
        int c = o * 256 + colmap(p);
        float2 v1 = *(const float2*)&wf1[(size_t)o * 512 + 2 * p];
        split_store(&g_W1H[c], &g_W1L[c], v1.x, v1.y);
        float2 v2 = *(const float2*)&wf2[(size_t)o * 512 + 2 * p];
        split_store(&g_W2H[c], &g_W2L[c], v2.x, v2.y);
    }
    for (int idx = tid; idx < 256 * 896; idx += stride) {
        int o = idx / 896, p = idx - o * 896;
        float2 v = *(const float2*)&wctx[(size_t)o * KC_ + 2 * p];
        split_store(&g_WCH[idx], &g_WCL[idx], v.x, v.y);
    }
    for (int idx = tid; idx < BT_ * 128; idx += stride) {
        int tok = idx >> 7, p = idx & 127;
        float2 v = *(const float2*)&x[(size_t)tok * D_ + 2 * p];
        split_store(&g_XH[idx], &g_XL[idx], v.x, v.y);
    }
    int w = tid >> 5, lane = tid & 31;
    if (w < M_) {
        const float* er = emb + (size_t)w * D_;
        double s = 0.0;
        for (int d = lane; d < D_; d += 32) { double v = (double)er[d]; s += v * v; }
        for (int off = 16; off; off >>= 1) s += __shfl_xor_sync(0xffffffffu, s, off);
        if (lane == 0) g_en[w] = (float)s;
    }
    {
        int b = blockIdx.x >> 6, sub = blockIdx.x & 63;
        const float* xb = x + (size_t)b * T_ * D_;
        const int n = (T_ - 1) * D_;
        float s = 0.f;
        for (int i = sub * 256 + threadIdx.x; i < n; i += 64 * 256) {
            float v = xb[i]; s += v * v;
        }
        __shared__ float red[256];
        red[threadIdx.x] = s; __syncthreads();
        for (int st = 128; st > 0; st >>= 1) {
            if (threadIdx.x < st) red[threadIdx.x] += red[threadIdx.x + st];
            __syncthreads();
        }
        if (threadIdx.x == 0) g_part[b][sub] = red[0];
    }
}

// ---------------- noisy context (coef inline) ----------------
__global__ void k_ctxn(const float* __restrict__ x, const float* __restrict__ noise,
                       const int* __restrict__ epo_i) {
    __shared__ float xs[32][33];
    __shared__ float s_coef;
    int b = blockIdx.z, bd = blockIdx.y * 32, bj = blockIdx.x * 32;
    if (threadIdx.y == 0) {
        int lane = threadIdx.x;
        float s = g_part[b][lane] + g_part[b][lane + 32];
        for (int off = 16; off; off >>= 1) s += __shfl_xor_sync(0xffffffffu, s, off);
        if (lane == 0) {
            int ei = *epo_i;
            double ef = (ei >= 0 && ei <= 1000000) ? (double)ei : (double)__int_as_float(ei);
            double mean = (double)s / (double)(D_ * L_);
            s_coef = (float)(0.5 * exp2(-ef / 10.0) * sqrt(mean));
        }
    }
    int t = bj + threadIdx.y - CTX_;
    float v = 0.f;
    if (t >= 0 && t < T_ - 1)
        v = x[((size_t)b * T_ + t) * D_ + bd + threadIdx.x];
    xs[threadIdx.y][threadIdx.x] = v;
    __syncthreads();
    int j = bj + threadIdx.x;
    if (j < L_) {
        int d = bd + threadIdx.y;
        float z = xs[threadIdx.x][threadIdx.y] + s_coef * noise[((size_t)b * D_ + d) * L_ + j];
        __half h = __float2half_rn(z);
        __half l = __float2half_rn(z - __half2float(h));
        size_t off = ((size_t)b * D_ + d) * LP + j;
        g_ZH[off] = h; g_ZL[off] = l;
    }
}

// ---------------- conv (R12-proven: M=128 tile, 2 CTA/SM, LDSM) ----------------
__global__ __launch_bounds__(256, 2) void k_convM() {
    __shared__ uint32_t AH[128][20], AL[128][20], BH[128][20], BL[128][20];
    int tid = threadIdx.x, wid = tid >> 5, lane = tid & 31;
    int bn = blockIdx.x * 128, bm = blockIdx.y * 128, b = blockIdx.z;
    const __half* zh = g_ZH + (size_t)b * D_ * LP;
    const __half* zl = g_ZL + (size_t)b * D_ * LP;
    int wm = wid >> 2, wn = wid & 3;
    int gr = lane >> 2, ctid = lane & 3;

    float acc[4][4][4];
#pragma unroll
    for (int i = 0; i < 4; i++)
#pragma unroll
        for (int j = 0; j < 4; j++)
#pragma unroll
            for (int r = 0; r < 4; r++) acc[i][j][r] = 0.f;

    uint32_t sAH = smem_u32(AH), sAL = smem_u32(AL);
    uint32_t sBH = smem_u32(BH), sBL = smem_u32(BL);
    uint32_t aAddr[4];
#pragma unroll
    for (int mf = 0; mf < 4; mf++) {
        int row = wm * 64 + mf * 16 + ((lane >> 3) & 1) * 8 + (lane & 7);
        aAddr[mf] = (uint32_t)row * 80 + ((lane >> 4) & 1) * 16;
    }
    uint32_t bAddr[2];
#pragma unroll
    for (int nfp = 0; nfp < 2; nfp++) {
        int row = wn * 32 + nfp * 16 + ((lane >> 4) & 1) * 8 + (lane & 7);
        bAddr[nfp] = (uint32_t)row * 80 + ((lane >> 3) & 1) * 16;
    }
    int arow = tid >> 1, ah8 = (tid & 1) * 8;
    int bt = tid & 127, ph = tid >> 7;

    for (int c = 0; c < 56; c++) {
        __syncthreads();
        {
            const uint32_t* sH = &g_WCH[(size_t)(bm + arow) * 896 + c * 16 + ah8];
            const uint32_t* sL = &g_WCL[(size_t)(bm + arow) * 896 + c * 16 + ah8];
            *(uint4*)&AH[arow][ah8]     = *(const uint4*)sH;
            *(uint4*)&AH[arow][ah8 + 4] = *(const uint4*)(sH + 4);
            *(uint4*)&AL[arow][ah8]     = *(const uint4*)sL;
            *(uint4*)&AL[arow][ah8 + 4] = *(const uint4*)(sL + 4);
        }
#pragma unroll
        for (int p = 0; p < 8; p++) {
            int pl = 8 * ph + p;
            int k0 = 32 * c + 2 * pl;
            int ci0 = k0 / 7, ck0 = k0 - 7 * ci0;
            int ci1 = ci0, ck1 = ck0 + 1;
            if (ck1 == 7) { ck1 = 0; ci1++; }
            int j0 = ci0 * LP + bn + bt + ck0;
            int j1 = ci1 * LP + bn + bt + ck1;
            BH[bt][pl] = pack_h2(zh[j0], zh[j1]);
            BL[bt][pl] = pack_h2(zl[j0], zl[j1]);
        }
        __syncthreads();
#pragma unroll
        for (int ks = 0; ks < 2; ks++) {
            uint32_t aH[4][4], aL[4][4];
#pragma unroll
            for (int mf = 0; mf < 4; mf++) {
                ldsm4(aH[mf], sAH + aAddr[mf] + ks * 32);
                ldsm4(aL[mf], sAL + aAddr[mf] + ks * 32);
            }
#pragma unroll
            for (int nfp = 0; nfp < 2; nfp++) {
                uint32_t bh4[4], bl4[4];
                ldsm4(bh4, sBH + bAddr[nfp] + ks * 32);
                ldsm4(bl4, sBL + bAddr[nfp] + ks * 32);
#pragma unroll
                for (int half = 0; half < 2; half++) {
                    int nf = nfp * 2 + half;
                    uint32_t bh[2] = {bh4[half * 2], bh4[half * 2 + 1]};
                    uint32_t bl[2] = {bl4[half * 2], bl4[half * 2 + 1]};
#pragma unroll
                    for (int mf = 0; mf < 4; mf++) {
                        mma16816(acc[mf][nf], aH[mf], bl);
                        mma16816(acc[mf][nf], aL[mf], bh);
                        mma16816(acc[mf][nf], aH[mf], bh);
                    }
                }
            }
        }
    }
#pragma unroll
    for (int mf = 0; mf < 4; mf++) {
        int o0 = bm + wm * 64 + mf * 16 + gr;
#pragma unroll
        for (int nf = 0; nf < 4; nf++) {
            int t0 = bn + wn * 32 + nf * 8 + 2 * ctid;
            size_t b0 = ((size_t)b * D_ + o0) * T_ + t0;
            size_t b8 = ((size_t)b * D_ + o0 + 8) * T_ + t0;
            split_store((uint32_t*)&g_COH[b0], (uint32_t*)&g_COL[b0],
                        acc[mf][nf][0], acc[mf][nf][1]);
            split_store((uint32_t*)&g_COH[b8], (uint32_t*)&g_COL[b8],
                        acc[mf][nf][2], acc[mf][nf][3]);
        }
    }
}

// ---------------- fuse: 512 threads / 16 warps, warp tile 32x64 ----------------
template<int WHICH>
__global__ __launch_bounds__(512, 1) void k_fuse2(const float* __restrict__ pa,
                                                  float* __restrict__ outp) {
    __shared__ uint32_t AH[128][20], AL[128][20];
    __shared__ int idxS[128];
    int tid = threadIdx.x, wid = tid >> 5, lane = tid & 31;
    int tok0 = blockIdx.x * 128;
    int b = tok0 >> 12, t0g = tok0 & (T_ - 1);
    int wm = wid >> 2, wn = wid & 3;           // 4 x 4 warps
    int gr = lane >> 2, ctid = lane & 3;
    if (WHICH == 1 && tid < 128) idxS[tid] = g_idx[tok0 + tid];

    float acc[2][8][4];
#pragma unroll
    for (int i = 0; i < 2; i++)
#pragma unroll
        for (int j = 0; j < 8; j++)
#pragma unroll
            for (int r = 0; r < 4; r++) acc[i][j][r] = 0.f;

    const uint32_t* WH = (WHICH == 0) ? g_W1H : g_W2H;
    const uint32_t* WL = (WHICH == 0) ? g_W1L : g_W2L;
    float* optr = (WHICH == 0) ? g_cur : outp;
    uint32_t sAH = smem_u32(AH), sAL = smem_u32(AL);
    uint32_t aAddr[2];
#pragma unroll
    for (int mf = 0; mf < 2; mf++) {
        int row = wm * 32 + mf * 16 + ((lane >> 3) & 1) * 8 + (lane & 7);
        aAddr[mf] = (uint32_t)row * 80 + ((lane >> 4) & 1) * 16;
    }
    int stok = tid >> 2, sq4 = (tid & 3) * 4;  // phase-1 staging: 512 thr x uint4
    int bt = tid & 127, ph = tid >> 7;         // phase-2: 4 pairs each
    __syncthreads();

    for (int cc = 0; cc < 16; cc++) {
        __syncthreads();
        if (cc < 8) {
            size_t rb = (WHICH == 0) ? (size_t)(tok0 + stok) * 128 : (size_t)idxS[stok] * 128;
            const uint32_t* sH = (WHICH == 0) ? &g_XH[rb + 16 * cc + sq4] : &g_EPH[rb + 16 * cc + sq4];
            const uint32_t* sL = (WHICH == 0) ? &g_XL[rb + 16 * cc + sq4] : &g_EPL[rb + 16 * cc + sq4];
            *(uint4*)&AH[stok][sq4] = *(const uint4*)sH;
            *(uint4*)&AL[stok][sq4] = *(const uint4*)sL;
        } else {
#pragma unroll
            for (int p = 0; p < 4; p++) {
                int pl = 4 * ph + p;
                int ch = cc * 32 - 256 + 2 * pl;
                size_t i0 = ((size_t)b * D_ + ch) * T_ + t0g + bt;
                size_t i1 = i0 + T_;
                AH[bt][pl] = pack_h2(g_COH[i0], g_COH[i1]);
                AL[bt][pl] = pack_h2(g_COL[i0], g_COL[i1]);
            }
        }
        __syncthreads();
#pragma unroll
        for (int ks = 0; ks < 2; ks++) {
            int sg = cc * 2 + ks;
            uint32_t aH[2][4], aL[2][4];
#pragma unroll
            for (int mf = 0; mf < 2; mf++) {
                ldsm4(aH[mf], sAH + aAddr[mf] + ks * 32);
                ldsm4(aL[mf], sAL + aAddr[mf] + ks * 32);
            }
#pragma unroll
            for (int nf = 0; nf < 8; nf++) {
                int n = wn * 64 + nf * 8 + gr;
                uint2 bh2 = *(const uint2*)&WH[(size_t)n * 256 + 8 * sg + 2 * ctid];
                uint2 bl2 = *(const uint2*)&WL[(size_t)n * 256 + 8 * sg + 2 * ctid];
                uint32_t bh[2] = {bh2.x, bh2.y}, bl[2] = {bl2.x, bl2.y};
#pragma unroll
                for (int mf = 0; mf < 2; mf++) {
                    mma16816(acc[mf][nf], aH[mf], bl);
                    mma16816(acc[mf][nf], aL[mf], bh);
                    mma16816(acc[mf][nf], aH[mf], bh);
                }
            }
        }
    }
    float av = *pa;
#pragma unroll
    for (int mf = 0; mf < 2; mf++) {
        int row = tok0 + wm * 32 + mf * 16 + gr;
#pragma unroll
        for (int nf = 0; nf < 8; nf++) {
            int col = wn * 64 + nf * 8 + 2 * ctid;
            float v0 = prelu_f(acc[mf][nf][0], av), v1 = prelu_f(acc[mf][nf][1], av);
            float v2 = prelu_f(acc[mf][nf][2], av), v3 = prelu_f(acc[mf][nf][3], av);
            *(float2*)&optr[(size_t)row * D_ + col]       = make_float2(v0, v1);
            *(float2*)&optr[(size_t)(row + 8) * D_ + col] = make_float2(v2, v3);
            if (WHICH == 0) {
                int cm = wn * 32 + nf * 4 + ctid;
                split_store(&g_CH[(size_t)row * 128 + cm], &g_CL[(size_t)row * 128 + cm], v0, v1);
                split_store(&g_CH[(size_t)(row + 8) * 128 + cm], &g_CL[(size_t)(row + 8) * 128 + cm], v2, v3);
            }
        }
    }
}

// ---------------- dist (R12-proven) ----------------
__global__ __launch_bounds__(256) void k_distM(const float* __restrict__ gu,
                                               float* __restrict__ dout) {
    __shared__ uint32_t AH[32][132], AL[32][132];
    __shared__ float pv[32][8];
    __shared__ int   pi[32][8];
    __shared__ float rs[32], zs[32], cns[32];
    int tid = threadIdx.x, wid = tid >> 5, lane = tid & 31;
    int wn = wid;
    int gr = lane >> 2, ctid = lane & 3;
    int row0g = blockIdx.x * 32;

    for (int idx = tid; idx < 32 * 32; idx += 256) {
        int row = idx >> 5, q = (idx & 31) * 4;
        *(uint4*)&AH[row][q] = *(const uint4*)&g_CH[(size_t)(row0g + row) * 128 + q];
        *(uint4*)&AL[row][q] = *(const uint4*)&g_CL[(size_t)(row0g + row) * 128 + q];
    }
#pragma unroll
    for (int i = 0; i < 4; i++) {
        const float* cr = g_cur + (size_t)(row0g + wid * 4 + i) * D_;
        float s = 0.f;
#pragma unroll
        for (int q = 0; q < 8; q++) { float v = cr[lane + q * 32]; s += v * v; }
#pragma unroll
        for (int off = 16; off; off >>= 1) s += __shfl_xor_sync(0xffffffffu, s, off);
        if (lane == 0) cns[wid * 4 + i] = s;
    }
    __syncthreads();

    uint32_t sAH = smem_u32(AH), sAL = smem_u32(AL);
    uint32_t aAddr[2];
#pragma unroll
    for (int mf = 0; mf < 2; mf++) {
        int row = mf * 16 + ((lane >> 3) & 1) * 8 + (lane & 7);
        aAddr[mf] = (uint32_t)row * 528 + ((lane >> 4) & 1) * 16;
    }

    float acc[2][16][4];
#pragma unroll
    for (int i = 0; i < 2; i++)
#pragma unroll
        for (int j = 0; j < 16; j++)
#pragma unroll
            for (int r = 0; r < 4; r++) acc[i][j][r] = 0.f;

#pragma unroll
    for (int s = 0; s < 16; s++) {
        uint32_t aH[2][4], aL[2][4];
#pragma unroll
        for (int mf = 0; mf < 2; mf++) {
            ldsm4(aH[mf], sAH + aAddr[mf] + s * 32);
            ldsm4(aL[mf], sAL + aAddr[mf] + s * 32);
        }
#pragma unroll
        for (int nf = 0; nf < 16; nf++) {
            int n = wn * 128 + nf * 8 + gr;
            uint2 bh2 = *(const uint2*)&g_EH[(size_t)n * 128 + 8 * s + 2 * ctid];
            uint2 bl2 = *(const uint2*)&g_EL[(size_t)n * 128 + 8 * s + 2 * ctid];
            uint32_t bh[2] = {bh2.x, bh2.y}, bl[2] = {bl2.x, bl2.y};
#pragma unroll
            for (int mf = 0; mf < 2; mf++) {
                mma16816(acc[mf][nf], aH[mf], bl);
                mma16816(acc[mf][nf], aL[mf], bh);
                mma16816(acc[mf][nf], aH[mf], bh);
            }
        }
    }

#pragma unroll
    for (int mf = 0; mf < 2; mf++)
#pragma unroll
        for (int nf = 0; nf < 16; nf++) {
            float2 e2 = *(const float2*)&g_en[wn * 128 + nf * 8 + 2 * ctid];
            float clo = cns[mf * 16 + gr], chi = cns[mf * 16 + gr + 8];
            acc[mf][nf][0] = -((clo + e2.x) - 2.f * acc[mf][nf][0]);
            acc[mf][nf][1] = -((clo + e2.y) - 2.f * acc[mf][nf][1]);
            acc[mf][nf][2] = -((chi + e2.x) - 2.f * acc[mf][nf][2]);
            acc[mf][nf][3] = -((chi + e2.y) - 2.f * acc[mf][nf][3]);
        }

    int rid[4] = {gr, gr + 8, 16 + gr, 24 + gr};

#pragma unroll
    for (int rr = 0; rr < 4; rr++) {
        int mf = rr >> 1, h = rr & 1;
        float mv = -3.4e38f; int mi = 0;
#pragma unroll
        for (int nf = 0; nf < 16; nf++) {
            int cb = wn * 128 + nf * 8 + 2 * ctid;
            float v0 = acc[mf][nf][h * 2], v1 = acc[mf][nf][h * 2 + 1];
            if (v0 > mv) { mv = v0; mi = cb; }
            if (v1 > mv) { mv = v1; mi = cb + 1; }
        }
#pragma unroll
        for (int off = 1; off <= 2; off <<= 1) {
            float ov = __shfl_xor_sync(0xffffffffu, mv, off);
            int   oi = __shfl_xor_sync(0xffffffffu, mi, off);
            if (ov > mv || (ov == mv && oi < mi)) { mv = ov; mi = oi; }
        }
        if (ctid == 0) { pv[rid[rr]][wn] = mv; pi[rid[rr]][wn] = mi; }
    }
    __syncthreads();
    if (tid < 32) {
        float mv = pv[tid][0]; int mi = pi[tid][0];
#pragma unroll
        for (int w = 1; w < 8; w++) {
            float ov = pv[tid][w]; int oi = pi[tid][w];
            if (ov > mv || (ov == mv && oi < mi)) { mv = ov; mi = oi; }
        }
        atomicAdd(&g_hist[mi], 1);
        rs[tid] = mv;
    }
    __syncthreads();

#pragma unroll
    for (int rr = 0; rr < 4; rr++) {
        int mf = rr >> 1, h = rr & 1;
        float rm = rs[rid[rr]];
        float s = 0.f;
#pragma unroll
        for (int nf = 0; nf < 16; nf++) {
            float e0 = __expf(acc[mf][nf][h * 2] - rm);
            float e1 = __expf(acc[mf][nf][h * 2 + 1] - rm);
            acc[mf][nf][h * 2] = e0; acc[mf][nf][h * 2 + 1] = e1;
            s += e0 + e1;
        }
#pragma unroll
        for (int off = 1; off <= 2; off <<= 1) s += __shfl_xor_sync(0xffffffffu, s, off);
        if (ctid == 0) pv[rid[rr]][wn] = s;
    }
    __syncthreads();
    if (tid < 32) {
        float z = 0.f;
#pragma unroll
        for (int w = 0; w < 8; w++) z += pv[tid][w];
        zs[tid] = 1.f / z;
    }
    __syncthreads();

    {
        float iz[4];
#pragma unroll
        for (int rr = 0; rr < 4; rr++) iz[rr] = zs[rid[rr]];
#pragma unroll
        for (int nf = 0; nf < 16; nf++) {
            float cs0 = acc[0][nf][0] * iz[0] + acc[0][nf][2] * iz[1]
                      + acc[1][nf][0] * iz[2] + acc[1][nf][2] * iz[3];
            float cs1 = acc[0][nf][1] * iz[0] + acc[0][nf][3] * iz[1]
                      + acc[1][nf][1] * iz[2] + acc[1][nf][3] * iz[3];
#pragma unroll
            for (int off = 4; off <= 16; off <<= 1) {
                cs0 += __shfl_xor_sync(0xffffffffu, cs0, off);
                cs1 += __shfl_xor_sync(0xffffffffu, cs1, off);
            }
            if (gr == 0) {
                int cb = wn * 128 + nf * 8 + 2 * ctid;
                atomicAdd(&g_avg[cb], cs0);
                atomicAdd(&g_avg[cb + 1], cs1);
            }
        }
    }

#pragma unroll
    for (int rr = 0; rr < 4; rr++) {
        int mf = rr >> 1, h = rr & 1;
        int row = row0g + rid[rr];
        float mv = -1.f; int mi = 0;
#pragma unroll
        for (int nf = 0; nf < 16; nf++) {
            int cb = wn * 128 + nf * 8 + 2 * ctid;
            float2 ug = *(const float2*)&gu[(size_t)row * M_ + cb];
            float u0 = fminf(fmaxf(ug.x, 1e-10f), 0.99999990f);
            float u1 = fminf(fmaxf(ug.y, 1e-10f), 0.99999990f);
            float t0 = neg_log_acc(u0), t1 = neg_log_acc(u1);
            float e0 = acc[mf][nf][h * 2], e1 = acc[mf][nf][h * 2 + 1];
            if (e0 > mv * t0) { mv = __fdividef(e0, t0); mi = cb; }
            if (e1 > mv * t1) { mv = __fdividef(e1, t1); mi = cb + 1; }
        }
#pragma unroll
        for (int off = 1; off <= 2; off <<= 1) {
            float ov = __shfl_xor_sync(0xffffffffu, mv, off);
            int   oi = __shfl_xor_sync(0xffffffffu, mi, off);
            if (ov > mv || (ov == mv && oi < mi)) { mv = ov; mi = oi; }
        }
        if (ctid == 0) { pv[rid[rr]][wn] = mv; pi[rid[rr]][wn] = mi; }
    }
    __syncthreads();
    if (tid < 32) {
        float mv = pv[tid][0]; int mi = pi[tid][0];
#pragma unroll
        for (int w = 1; w < 8; w++) {
            float ov = pv[tid][w]; int oi = pi[tid][w];
            if (ov > mv || (ov == mv && oi < mi)) { mv = ov; mi = oi; }
        }
        g_idx[row0g + tid] = mi;
        dout[OFF_IND + row0g + tid] = (float)mi;
    }
}

__global__ void k_perp(float* __restrict__ dout) {
    __shared__ float red[1024];
    int m = threadIdx.x;
    float p = (float)g_hist[m] / 32768.f;
    red[m] = -p * log2f(p + 1e-10f);
    __syncthreads();
    for (int st = 512; st > 0; st >>= 1) {
        if (m < st) red[m] += red[m + st];
        __syncthreads();
    }
    if (m == 0) dout[OFF_CP] = red[0];
    __syncthreads();
    float q = g_avg[m] / 32768.f;
    red[m] = -q * log2f(q + 1e-10f);
    __syncthreads();
    for (int st = 512; st > 0; st >>= 1) {
        if (m < st) red[m] += red[m + st];
        __syncthreads();
    }
    if (m == 0) dout[OFF_PP] = red[0];
}

extern "C" void kernel_launch(void* const* d_in, const int* in_sizes, int n_in,
                              void* d_out, int out_size) {
    const float* x     = (const float*)d_in[0];
    const float* noise = (const float*)d_in[1];
    const float* gu    = (const float*)d_in[2];
    const int*   epo   = (const int*)d_in[3];
    const float* emb   = (const float*)d_in[4];
    const float* wctx  = (const float*)d_in[5];
    const float* wf1   = (const float*)d_in[6];
    const float* a1    = (const float*)d_in[7];
    const float* wf2   = (const float*)d_in[8];
    const float* a2    = (const float*)d_in[9];
    float* out = (float*)d_out;

    k_prep<<<512, 256>>>(emb, wf1, wf2, x, wctx);
    k_ctxn<<<dim3((L_ + 31) / 32, D_ / 32, B_), dim3(32, 32)>>>(x, noise, epo);
    k_convM<<<dim3(T_ / 128, D_ / 128, B_), 256>>>();
    k_fuse2<0><<<BT_ / 128, 512>>>(a1, out);
    k_distM<<<BT_ / 32, 256>>>(gu, out);
    k_perp<<<1, 1024>>>(out);
    k_fuse2<1><<<BT_ / 128, 512>>>(a2, out);
}

// round 16
// speedup vs baseline: 1.0450x; 1.0146x over previous
#include <cuda_runtime.h>
#include <cuda_fp16.h>
#include <math.h>
#include <stdint.h>

#define B_   8
#define T_   4096
#define D_   256
#define M_   1024
#define CTX_ 7
#define L_   4102
#define LP   4104
#define BT_  32768
#define KC_  1792

#define OFF_CP  8388608
#define OFF_PP  8388609
#define OFF_IND 8388610

__device__ __half g_ZH[B_ * D_ * LP], g_ZL[B_ * D_ * LP];
__device__ __half g_COH[B_ * D_ * T_], g_COL[B_ * D_ * T_];
__device__ float  g_cur[BT_ * D_];
__device__ uint32_t g_WCH[256 * 896], g_WCL[256 * 896];   // PLAIN (conv A)
__device__ uint32_t g_XH[BT_ * 128],  g_XL[BT_ * 128];    // PLAIN (fuse1 A staging)
__device__ uint32_t g_CH[BT_ * 128],  g_CL[BT_ * 128];    // PLAIN (dist A)
__device__ uint32_t g_EH[M_ * 128],   g_EL[M_ * 128];     // colmap (dist B LDG)
__device__ uint32_t g_EPH[M_ * 128],  g_EPL[M_ * 128];    // PLAIN (fuse2 A staging)
__device__ uint32_t g_W1H[256 * 256], g_W1L[256 * 256];   // colmap (fuse B LDG)
__device__ uint32_t g_W2H[256 * 256], g_W2L[256 * 256];
__device__ float g_en[M_];
__device__ float g_part[B_][64];
__device__ int   g_idx[BT_];
__device__ int   g_hist[M_];
__device__ float g_avg[M_];

__device__ __forceinline__ float prelu_f(float v, float a) { return v >= 0.f ? v : a * v; }

__device__ __forceinline__ float neg_log_acc(float u) {
    if (u > 0.9f) {
        float d = 1.0f - u;
        return d * (1.f + d * (0.5f + d * (0.33333334f + d * (0.25f + d * (0.2f + d * 0.16666667f)))));
    }
    return -logf(u);
}

__device__ __forceinline__ uint32_t pack_h2(__half a, __half b) {
    __half2 h = __halves2half2(a, b);
    return *(uint32_t*)&h;
}
__device__ __forceinline__ uint32_t smem_u32(const void* p) {
    uint32_t a;
    asm("{ .reg .u64 t; cvta.to.shared.u64 t, %1; cvt.u32.u64 %0, t; }" : "=r"(a) : "l"(p));
    return a;
}
__device__ __forceinline__ void mma16816(float* d, const uint32_t* a, const uint32_t* b) {
    asm volatile(
        "mma.sync.aligned.m16n8k16.row.col.f32.f16.f16.f32 "
        "{%0,%1,%2,%3}, {%4,%5,%6,%7}, {%8,%9}, {%0,%1,%2,%3};"
        : "+f"(d[0]), "+f"(d[1]), "+f"(d[2]), "+f"(d[3])
        : "r"(a[0]), "r"(a[1]), "r"(a[2]), "r"(a[3]), "r"(b[0]), "r"(b[1]));
}
__device__ __forceinline__ void ldsm4(uint32_t* r, uint32_t addr) {
    asm volatile("ldmatrix.sync.aligned.m8n8.x4.shared.b16 {%0,%1,%2,%3}, [%4];"
                 : "=r"(r[0]), "=r"(r[1]), "=r"(r[2]), "=r"(r[3]) : "r"(addr));
}
__device__ __forceinline__ void split_store(uint32_t* H, uint32_t* L, float x0, float x1) {
    __half h0 = __float2half_rn(x0), h1 = __float2half_rn(x1);
    __half l0 = __float2half_rn(x0 - __half2float(h0));
    __half l1 = __float2half_rn(x1 - __half2float(h1));
    *H = pack_h2(h0, h1);
    *L = pack_h2(l0, l1);
}
__device__ __forceinline__ int colmap(int p) {
    int s = p >> 3, r = p & 7;
    return 8 * s + ((r & 4) ? ((r - 4) * 2 + 1) : (r * 2));
}

// ---------------- merged prep ----------------
__global__ void k_prep(const float* __restrict__ emb, const float* __restrict__ wf1,
                       const float* __restrict__ wf2, const float* __restrict__ x,
                       const float* __restrict__ wctx) {
    int tid = blockIdx.x * blockDim.x + threadIdx.x;
    int stride = gridDim.x * blockDim.x;
    if (tid < M_) { g_hist[tid] = 0; g_avg[tid] = 0.f; }
    for (int idx = tid; idx < M_ * 128; idx += stride) {
        int m = idx >> 7, p = idx & 127;
        float2 v = *(const float2*)&emb[(size_t)m * D_ + 2 * p];
        int c = m * 128 + colmap(p);
        split_store(&g_EH[c], &g_EL[c], v.x, v.y);
        split_store(&g_EPH[idx], &g_EPL[idx], v.x, v.y);
    }
    for (int idx = tid; idx < 256 * 256; idx += stride) {
        int o = idx >> 8, p = idx & 255;
        int c = o * 256 + colmap(p);
        float2 v1 = *(const float2*)&wf1[(size_t)o * 512 + 2 * p];
        split_store(&g_W1H[c], &g_W1L[c], v1.x, v1.y);
        float2 v2 = *(const float2*)&wf2[(size_t)o * 512 + 2 * p];
        split_store(&g_W2H[c], &g_W2L[c], v2.x, v2.y);
    }
    for (int idx = tid; idx < 256 * 896; idx += stride) {
        int o = idx / 896, p = idx - o * 896;
        float2 v = *(const float2*)&wctx[(size_t)o * KC_ + 2 * p];
        split_store(&g_WCH[idx], &g_WCL[idx], v.x, v.y);
    }
    for (int idx = tid; idx < BT_ * 128; idx += stride) {
        int tok = idx >> 7, p = idx & 127;
        float2 v = *(const float2*)&x[(size_t)tok * D_ + 2 * p];
        split_store(&g_XH[idx], &g_XL[idx], v.x, v.y);
    }
    int w = tid >> 5, lane = tid & 31;
    if (w < M_) {
        const float* er = emb + (size_t)w * D_;
        double s = 0.0;
        for (int d = lane; d < D_; d += 32) { double v = (double)er[d]; s += v * v; }
        for (int off = 16; off; off >>= 1) s += __shfl_xor_sync(0xffffffffu, s, off);
        if (lane == 0) g_en[w] = (float)s;
    }
    {
        int b = blockIdx.x >> 6, sub = blockIdx.x & 63;
        const float* xb = x + (size_t)b * T_ * D_;
        const int n = (T_ - 1) * D_;
        float s = 0.f;
        for (int i = sub * 256 + threadIdx.x; i < n; i += 64 * 256) {
            float v = xb[i]; s += v * v;
        }
        __shared__ float red[256];
        red[threadIdx.x] = s; __syncthreads();
        for (int st = 128; st > 0; st >>= 1) {
            if (threadIdx.x < st) red[threadIdx.x] += red[threadIdx.x + st];
            __syncthreads();
        }
        if (threadIdx.x == 0) g_part[b][sub] = red[0];
    }
}

// ---------------- noisy context (coef inline) ----------------
__global__ void k_ctxn(const float* __restrict__ x, const float* __restrict__ noise,
                       const int* __restrict__ epo_i) {
    __shared__ float xs[32][33];
    __shared__ float s_coef;
    int b = blockIdx.z, bd = blockIdx.y * 32, bj = blockIdx.x * 32;
    if (threadIdx.y == 0) {
        int lane = threadIdx.x;
        float s = g_part[b][lane] + g_part[b][lane + 32];
        for (int off = 16; off; off >>= 1) s += __shfl_xor_sync(0xffffffffu, s, off);
        if (lane == 0) {
            int ei = *epo_i;
            double ef = (ei >= 0 && ei <= 1000000) ? (double)ei : (double)__int_as_float(ei);
            double mean = (double)s / (double)(D_ * L_);
            s_coef = (float)(0.5 * exp2(-ef / 10.0) * sqrt(mean));
        }
    }
    int t = bj + threadIdx.y - CTX_;
    float v = 0.f;
    if (t >= 0 && t < T_ - 1)
        v = x[((size_t)b * T_ + t) * D_ + bd + threadIdx.x];
    xs[threadIdx.y][threadIdx.x] = v;
    __syncthreads();
    int j = bj + threadIdx.x;
    if (j < L_) {
        int d = bd + threadIdx.y;
        float z = xs[threadIdx.x][threadIdx.y] + s_coef * noise[((size_t)b * D_ + d) * L_ + j];
        __half h = __float2half_rn(z);
        __half l = __float2half_rn(z - __half2float(h));
        size_t off = ((size_t)b * D_ + d) * LP + j;
        g_ZH[off] = h; g_ZL[off] = l;
    }
}

// ---------------- conv (R12-proven) ----------------
__global__ __launch_bounds__(256, 2) void k_convM() {
    __shared__ uint32_t AH[128][20], AL[128][20], BH[128][20], BL[128][20];
    int tid = threadIdx.x, wid = tid >> 5, lane = tid & 31;
    int bn = blockIdx.x * 128, bm = blockIdx.y * 128, b = blockIdx.z;
    const __half* zh = g_ZH + (size_t)b * D_ * LP;
    const __half* zl = g_ZL + (size_t)b * D_ * LP;
    int wm = wid >> 2, wn = wid & 3;
    int gr = lane >> 2, ctid = lane & 3;

    float acc[4][4][4];
#pragma unroll
    for (int i = 0; i < 4; i++)
#pragma unroll
        for (int j = 0; j < 4; j++)
#pragma unroll
            for (int r = 0; r < 4; r++) acc[i][j][r] = 0.f;

    uint32_t sAH = smem_u32(AH), sAL = smem_u32(AL);
    uint32_t sBH = smem_u32(BH), sBL = smem_u32(BL);
    uint32_t aAddr[4];
#pragma unroll
    for (int mf = 0; mf < 4; mf++) {
        int row = wm * 64 + mf * 16 + ((lane >> 3) & 1) * 8 + (lane & 7);
        aAddr[mf] = (uint32_t)row * 80 + ((lane >> 4) & 1) * 16;
    }
    uint32_t bAddr[2];
#pragma unroll
    for (int nfp = 0; nfp < 2; nfp++) {
        int row = wn * 32 + nfp * 16 + ((lane >> 4) & 1) * 8 + (lane & 7);
        bAddr[nfp] = (uint32_t)row * 80 + ((lane >> 3) & 1) * 16;
    }
    int arow = tid >> 1, ah8 = (tid & 1) * 8;
    int bt = tid & 127, ph = tid >> 7;

    for (int c = 0; c < 56; c++) {
        __syncthreads();
        {
            const uint32_t* sH = &g_WCH[(size_t)(bm + arow) * 896 + c * 16 + ah8];
            const uint32_t* sL = &g_WCL[(size_t)(bm + arow) * 896 + c * 16 + ah8];
            *(uint4*)&AH[arow][ah8]     = *(const uint4*)sH;
            *(uint4*)&AH[arow][ah8 + 4] = *(const uint4*)(sH + 4);
            *(uint4*)&AL[arow][ah8]     = *(const uint4*)sL;
            *(uint4*)&AL[arow][ah8 + 4] = *(const uint4*)(sL + 4);
        }
#pragma unroll
        for (int p = 0; p < 8; p++) {
            int pl = 8 * ph + p;
            int k0 = 32 * c + 2 * pl;
            int ci0 = k0 / 7, ck0 = k0 - 7 * ci0;
            int ci1 = ci0, ck1 = ck0 + 1;
            if (ck1 == 7) { ck1 = 0; ci1++; }
            int j0 = ci0 * LP + bn + bt + ck0;
            int j1 = ci1 * LP + bn + bt + ck1;
            BH[bt][pl] = pack_h2(zh[j0], zh[j1]);
            BL[bt][pl] = pack_h2(zl[j0], zl[j1]);
        }
        __syncthreads();
#pragma unroll
        for (int ks = 0; ks < 2; ks++) {
            uint32_t aH[4][4], aL[4][4];
#pragma unroll
            for (int mf = 0; mf < 4; mf++) {
                ldsm4(aH[mf], sAH + aAddr[mf] + ks * 32);
                ldsm4(aL[mf], sAL + aAddr[mf] + ks * 32);
            }
#pragma unroll
            for (int nfp = 0; nfp < 2; nfp++) {
                uint32_t bh4[4], bl4[4];
                ldsm4(bh4, sBH + bAddr[nfp] + ks * 32);
                ldsm4(bl4, sBL + bAddr[nfp] + ks * 32);
#pragma unroll
                for (int half = 0; half < 2; half++) {
                    int nf = nfp * 2 + half;
                    uint32_t bh[2] = {bh4[half * 2], bh4[half * 2 + 1]};
                    uint32_t bl[2] = {bl4[half * 2], bl4[half * 2 + 1]};
#pragma unroll
                    for (int mf = 0; mf < 4; mf++) {
                        mma16816(acc[mf][nf], aH[mf], bl);
                        mma16816(acc[mf][nf], aL[mf], bh);
                        mma16816(acc[mf][nf], aH[mf], bh);
                    }
                }
            }
        }
    }
#pragma unroll
    for (int mf = 0; mf < 4; mf++) {
        int o0 = bm + wm * 64 + mf * 16 + gr;
#pragma unroll
        for (int nf = 0; nf < 4; nf++) {
            int t0 = bn + wn * 32 + nf * 8 + 2 * ctid;
            size_t b0 = ((size_t)b * D_ + o0) * T_ + t0;
            size_t b8 = ((size_t)b * D_ + o0 + 8) * T_ + t0;
            split_store((uint32_t*)&g_COH[b0], (uint32_t*)&g_COL[b0],
                        acc[mf][nf][0], acc[mf][nf][1]);
            split_store((uint32_t*)&g_COH[b8], (uint32_t*)&g_COL[b8],
                        acc[mf][nf][2], acc[mf][nf][3]);
        }
    }
}

// ---------------- fuse: 256 threads, 2 CTA/SM, CTA tile 64 tok x 256 out ----------------
template<int WHICH>
__global__ __launch_bounds__(256, 2) void k_fuse2(const float* __restrict__ pa,
                                                  float* __restrict__ outp) {
    __shared__ uint32_t AH[64][20], AL[64][20];
    __shared__ int idxS[64];
    int tid = threadIdx.x, wid = tid >> 5, lane = tid & 31;
    int tok0 = blockIdx.x * 64;
    int b = tok0 >> 12, t0g = tok0 & (T_ - 1);
    int wm = wid >> 2, wn = wid & 3;           // 2 x 4 warps
    int gr = lane >> 2, ctid = lane & 3;
    if (WHICH == 1 && tid < 64) idxS[tid] = g_idx[tok0 + tid];

    float acc[2][8][4];
#pragma unroll
    for (int i = 0; i < 2; i++)
#pragma unroll
        for (int j = 0; j < 8; j++)
#pragma unroll
            for (int r = 0; r < 4; r++) acc[i][j][r] = 0.f;

    const uint32_t* WH = (WHICH == 0) ? g_W1H : g_W2H;
    const uint32_t* WL = (WHICH == 0) ? g_W1L : g_W2L;
    float* optr = (WHICH == 0) ? g_cur : outp;
    uint32_t sAH = smem_u32(AH), sAL = smem_u32(AL);
    uint32_t aAddr[2];
#pragma unroll
    for (int mf = 0; mf < 2; mf++) {
        int row = wm * 32 + mf * 16 + ((lane >> 3) & 1) * 8 + (lane & 7);
        aAddr[mf] = (uint32_t)row * 80 + ((lane >> 4) & 1) * 16;
    }
    int stok = tid >> 2, sq4 = (tid & 3) * 4;  // phase-1: one uint4 per thread
    int bt = tid & 63, ph = tid >> 6;          // phase-2: 4 pairs per thread
    __syncthreads();

    for (int cc = 0; cc < 16; cc++) {
        __syncthreads();
        if (cc < 8) {
            size_t rb = (WHICH == 0) ? (size_t)(tok0 + stok) * 128 : (size_t)idxS[stok] * 128;
            const uint32_t* sH = (WHICH == 0) ? &g_XH[rb + 16 * cc + sq4] : &g_EPH[rb + 16 * cc + sq4];
            const uint32_t* sL = (WHICH == 0) ? &g_XL[rb + 16 * cc + sq4] : &g_EPL[rb + 16 * cc + sq4];
            *(uint4*)&AH[stok][sq4] = *(const uint4*)sH;
            *(uint4*)&AL[stok][sq4] = *(const uint4*)sL;
        } else {
#pragma unroll
            for (int p = 0; p < 4; p++) {
                int pl = 4 * ph + p;
                int ch = cc * 32 - 256 + 2 * pl;
                size_t i0 = ((size_t)b * D_ + ch) * T_ + t0g + bt;
                size_t i1 = i0 + T_;
                AH[bt][pl] = pack_h2(g_COH[i0], g_COH[i1]);
                AL[bt][pl] = pack_h2(g_COL[i0], g_COL[i1]);
            }
        }
        __syncthreads();
#pragma unroll
        for (int ks = 0; ks < 2; ks++) {
            int sg = cc * 2 + ks;
            uint32_t aH[2][4], aL[2][4];
#pragma unroll
            for (int mf = 0; mf < 2; mf++) {
                ldsm4(aH[mf], sAH + aAddr[mf] + ks * 32);
                ldsm4(aL[mf], sAL + aAddr[mf] + ks * 32);
            }
#pragma unroll
            for (int nf = 0; nf < 8; nf++) {
                int n = wn * 64 + nf * 8 + gr;
                uint2 bh2 = *(const uint2*)&WH[(size_t)n * 256 + 8 * sg + 2 * ctid];
                uint2 bl2 = *(const uint2*)&WL[(size_t)n * 256 + 8 * sg + 2 * ctid];
                uint32_t bh[2] = {bh2.x, bh2.y}, bl[2] = {bl2.x, bl2.y};
#pragma unroll
                for (int mf = 0; mf < 2; mf++) {
                    mma16816(acc[mf][nf], aH[mf], bl);
                    mma16816(acc[mf][nf], aL[mf], bh);
                    mma16816(acc[mf][nf], aH[mf], bh);
                }
            }
        }
    }
    float av = *pa;
#pragma unroll
    for (int mf = 0; mf < 2; mf++) {
        int row = tok0 + wm * 32 + mf * 16 + gr;
#pragma unroll
        for (int nf = 0; nf < 8; nf++) {
            int col = wn * 64 + nf * 8 + 2 * ctid;
            float v0 = prelu_f(acc[mf][nf][0], av), v1 = prelu_f(acc[mf][nf][1], av);
            float v2 = prelu_f(acc[mf][nf][2], av), v3 = prelu_f(acc[mf][nf][3], av);
            *(float2*)&optr[(size_t)row * D_ + col]       = make_float2(v0, v1);
            *(float2*)&optr[(size_t)(row + 8) * D_ + col] = make_float2(v2, v3);
            if (WHICH == 0) {
                int cm = wn * 32 + nf * 4 + ctid;
                split_store(&g_CH[(size_t)row * 128 + cm], &g_CL[(size_t)row * 128 + cm], v0, v1);
                split_store(&g_CH[(size_t)(row + 8) * 128 + cm], &g_CL[(size_t)(row + 8) * 128 + cm], v2, v3);
            }
        }
    }
}

// ---------------- dist (R12-proven) ----------------
__global__ __launch_bounds__(256) void k_distM(const float* __restrict__ gu,
                                               float* __restrict__ dout) {
    __shared__ uint32_t AH[32][132], AL[32][132];
    __shared__ float pv[32][8];
    __shared__ int   pi[32][8];
    __shared__ float rs[32], zs[32], cns[32];
    int tid = threadIdx.x, wid = tid >> 5, lane = tid & 31;
    int wn = wid;
    int gr = lane >> 2, ctid = lane & 3;
    int row0g = blockIdx.x * 32;

    for (int idx = tid; idx < 32 * 32; idx += 256) {
        int row = idx >> 5, q = (idx & 31) * 4;
        *(uint4*)&AH[row][q] = *(const uint4*)&g_CH[(size_t)(row0g + row) * 128 + q];
        *(uint4*)&AL[row][q] = *(const uint4*)&g_CL[(size_t)(row0g + row) * 128 + q];
    }
#pragma unroll
    for (int i = 0; i < 4; i++) {
        const float* cr = g_cur + (size_t)(row0g + wid * 4 + i) * D_;
        float s = 0.f;
#pragma unroll
        for (int q = 0; q < 8; q++) { float v = cr[lane + q * 32]; s += v * v; }
#pragma unroll
        for (int off = 16; off; off >>= 1) s += __shfl_xor_sync(0xffffffffu, s, off);
        if (lane == 0) cns[wid * 4 + i] = s;
    }
    __syncthreads();

    uint32_t sAH = smem_u32(AH), sAL = smem_u32(AL);
    uint32_t aAddr[2];
#pragma unroll
    for (int mf = 0; mf < 2; mf++) {
        int row = mf * 16 + ((lane >> 3) & 1) * 8 + (lane & 7);
        aAddr[mf] = (uint32_t)row * 528 + ((lane >> 4) & 1) * 16;
    }

    float acc[2][16][4];
#pragma unroll
    for (int i = 0; i < 2; i++)
#pragma unroll
        for (int j = 0; j < 16; j++)
#pragma unroll
            for (int r = 0; r < 4; r++) acc[i][j][r] = 0.f;

#pragma unroll
    for (int s = 0; s < 16; s++) {
        uint32_t aH[2][4], aL[2][4];
#pragma unroll
        for (int mf = 0; mf < 2; mf++) {
            ldsm4(aH[mf], sAH + aAddr[mf] + s * 32);
            ldsm4(aL[mf], sAL + aAddr[mf] + s * 32);
        }
#pragma unroll
        for (int nf = 0; nf < 16; nf++) {
            int n = wn * 128 + nf * 8 + gr;
            uint2 bh2 = *(const uint2*)&g_EH[(size_t)n * 128 + 8 * s + 2 * ctid];
            uint2 bl2 = *(const uint2*)&g_EL[(size_t)n * 128 + 8 * s + 2 * ctid];
            uint32_t bh[2] = {bh2.x, bh2.y}, bl[2] = {bl2.x, bl2.y};
#pragma unroll
            for (int mf = 0; mf < 2; mf++) {
                mma16816(acc[mf][nf], aH[mf], bl);
                mma16816(acc[mf][nf], aL[mf], bh);
                mma16816(acc[mf][nf], aH[mf], bh);
            }
        }
    }

#pragma unroll
    for (int mf = 0; mf < 2; mf++)
#pragma unroll
        for (int nf = 0; nf < 16; nf++) {
            float2 e2 = *(const float2*)&g_en[wn * 128 + nf * 8 + 2 * ctid];
            float clo = cns[mf * 16 + gr], chi = cns[mf * 16 + gr + 8];
            acc[mf][nf][0] = -((clo + e2.x) - 2.f * acc[mf][nf][0]);
            acc[mf][nf][1] = -((clo + e2.y) - 2.f * acc[mf][nf][1]);
            acc[mf][nf][2] = -((chi + e2.x) - 2.f * acc[mf][nf][2]);
            acc[mf][nf][3] = -((chi + e2.y) - 2.f * acc[mf][nf][3]);
        }

    int rid[4] = {gr, gr + 8, 16 + gr, 24 + gr};

#pragma unroll
    for (int rr = 0; rr < 4; rr++) {
        int mf = rr >> 1, h = rr & 1;
        float mv = -3.4e38f; int mi = 0;
#pragma unroll
        for (int nf = 0; nf < 16; nf++) {
            int cb = wn * 128 + nf * 8 + 2 * ctid;
            float v0 = acc[mf][nf][h * 2], v1 = acc[mf][nf][h * 2 + 1];
            if (v0 > mv) { mv = v0; mi = cb; }
            if (v1 > mv) { mv = v1; mi = cb + 1; }
        }
#pragma unroll
        for (int off = 1; off <= 2; off <<= 1) {
            float ov = __shfl_xor_sync(0xffffffffu, mv, off);
            int   oi = __shfl_xor_sync(0xffffffffu, mi, off);
            if (ov > mv || (ov == mv && oi < mi)) { mv = ov; mi = oi; }
        }
        if (ctid == 0) { pv[rid[rr]][wn] = mv; pi[rid[rr]][wn] = mi; }
    }
    __syncthreads();
    if (tid < 32) {
        float mv = pv[tid][0]; int mi = pi[tid][0];
#pragma unroll
        for (int w = 1; w < 8; w++) {
            float ov = pv[tid][w]; int oi = pi[tid][w];
            if (ov > mv || (ov == mv && oi < mi)) { mv = ov; mi = oi; }
        }
        atomicAdd(&g_hist[mi], 1);
        rs[tid] = mv;
    }
    __syncthreads();

#pragma unroll
    for (int rr = 0; rr < 4; rr++) {
        int mf = rr >> 1, h = rr & 1;
        float rm = rs[rid[rr]];
        float s = 0.f;
#pragma unroll
        for (int nf = 0; nf < 16; nf++) {
            float e0 = __expf(acc[mf][nf][h * 2] - rm);
            float e1 = __expf(acc[mf][nf][h * 2 + 1] - rm);
            acc[mf][nf][h * 2] = e0; acc[mf][nf][h * 2 + 1] = e1;
            s += e0 + e1;
        }
#pragma unroll
        for (int off = 1; off <= 2; off <<= 1) s += __shfl_xor_sync(0xffffffffu, s, off);
        if (ctid == 0) pv[rid[rr]][wn] = s;
    }
    __syncthreads();
    if (tid < 32) {
        float z = 0.f;
#pragma unroll
        for (int w = 0; w < 8; w++) z += pv[tid][w];
        zs[tid] = 1.f / z;
    }
    __syncthreads();

    {
        float iz[4];
#pragma unroll
        for (int rr = 0; rr < 4; rr++) iz[rr] = zs[rid[rr]];
#pragma unroll
        for (int nf = 0; nf < 16; nf++) {
            float cs0 = acc[0][nf][0] * iz[0] + acc[0][nf][2] * iz[1]
                      + acc[1][nf][0] * iz[2] + acc[1][nf][2] * iz[3];
            float cs1 = acc[0][nf][1] * iz[0] + acc[0][nf][3] * iz[1]
                      + acc[1][nf][1] * iz[2] + acc[1][nf][3] * iz[3];
#pragma unroll
            for (int off = 4; off <= 16; off <<= 1) {
                cs0 += __shfl_xor_sync(0xffffffffu, cs0, off);
                cs1 += __shfl_xor_sync(0xffffffffu, cs1, off);
            }
            if (gr == 0) {
                int cb = wn * 128 + nf * 8 + 2 * ctid;
                atomicAdd(&g_avg[cb], cs0);
                atomicAdd(&g_avg[cb + 1], cs1);
            }
        }
    }

#pragma unroll
    for (int rr = 0; rr < 4; rr++) {
        int mf = rr >> 1, h = rr & 1;
        int row = row0g + rid[rr];
        float mv = -1.f; int mi = 0;
#pragma unroll
        for (int nf = 0; nf < 16; nf++) {
            int cb = wn * 128 + nf * 8 + 2 * ctid;
            float2 ug = *(const float2*)&gu[(size_t)row * M_ + cb];
            float u0 = fminf(fmaxf(ug.x, 1e-10f), 0.99999990f);
            float u1 = fminf(fmaxf(ug.y, 1e-10f), 0.99999990f);
            float t0 = neg_log_acc(u0), t1 = neg_log_acc(u1);
            float e0 = acc[mf][nf][h * 2], e1 = acc[mf][nf][h * 2 + 1];
            if (e0 > mv * t0) { mv = __fdividef(e0, t0); mi = cb; }
            if (e1 > mv * t1) { mv = __fdividef(e1, t1); mi = cb + 1; }
        }
#pragma unroll
        for (int off = 1; off <= 2; off <<= 1) {
            float ov = __shfl_xor_sync(0xffffffffu, mv, off);
            int   oi = __shfl_xor_sync(0xffffffffu, mi, off);
            if (ov > mv || (ov == mv && oi < mi)) { mv = ov; mi = oi; }
        }
        if (ctid == 0) { pv[rid[rr]][wn] = mv; pi[rid[rr]][wn] = mi; }
    }
    __syncthreads();
    if (tid < 32) {
        float mv = pv[tid][0]; int mi = pi[tid][0];
#pragma unroll
        for (int w = 1; w < 8; w++) {
            float ov = pv[tid][w]; int oi = pi[tid][w];
            if (ov > mv || (ov == mv && oi < mi)) { mv = ov; mi = oi; }
        }
        g_idx[row0g + tid] = mi;
        dout[OFF_IND + row0g + tid] = (float)mi;
    }
}

__global__ void k_perp(float* __restrict__ dout) {
    __shared__ float red[1024];
    int m = threadIdx.x;
    float p = (float)g_hist[m] / 32768.f;
    red[m] = -p * log2f(p + 1e-10f);
    __syncthreads();
    for (int st = 512; st > 0; st >>= 1) {
        if (m < st) red[m] += red[m + st];
        __syncthreads();
    }
    if (m == 0) dout[OFF_CP] = red[0];
    __syncthreads();
    float q = g_avg[m] / 32768.f;
    red[m] = -q * log2f(q + 1e-10f);
    __syncthreads();
    for (int st = 512; st > 0; st >>= 1) {
        if (m < st) red[m] += red[m + st];
        __syncthreads();
    }
    if (m == 0) dout[OFF_PP] = red[0];
}

extern "C" void kernel_launch(void* const* d_in, const int* in_sizes, int n_in,
                              void* d_out, int out_size) {
    const float* x     = (const float*)d_in[0];
    const float* noise = (const float*)d_in[1];
    const float* gu    = (const float*)d_in[2];
    const int*   epo   = (const int*)d_in[3];
    const float* emb   = (const float*)d_in[4];
    const float* wctx  = (const float*)d_in[5];
    const float* wf1   = (const float*)d_in[6];
    const float* a1    = (const float*)d_in[7];
    const float* wf2   = (const float*)d_in[8];
    const float* a2    = (const float*)d_in[9];
    float* out = (float*)d_out;

    k_prep<<<512, 256>>>(emb, wf1, wf2, x, wctx);
    k_ctxn<<<dim3((L_ + 31) / 32, D_ / 32, B_), dim3(32, 32)>>>(x, noise, epo);
    k_convM<<<dim3(T_ / 128, D_ / 128, B_), 256>>>();
    k_fuse2<0><<<BT_ / 64, 256>>>(a1, out);
    k_distM<<<BT_ / 32, 256>>>(gu, out);
    k_perp<<<1, 1024>>>(out);
    k_fuse2<1><<<BT_ / 64, 256>>>(a2, out);
}